// round 7
// baseline (speedup 1.0000x reference)
#include <cuda_runtime.h>
#include <math.h>
#include <stdint.h>

#define NN 100000
#define DD 128
#define CC 16
#define SS 16
#define EE 3200000
#define KK 64
#define NIT 4

// ---------------- persistent device state (reset every launch) ----------------
__device__ unsigned int        g_nbr[NN];      // per-node 16-bit class neighbor mask (accumulative)
__device__ unsigned char       g_known[NN];
__device__ float               g_hx[CC * DD];
__device__ float               g_hxn[CC * DD]; // normalized hx
__device__ int                 g_last[CC * KK];
__device__ int                 g_candCnt[CC];
__device__ unsigned long long  g_candKeys[(size_t)CC * NN]; // 12.8 MB scratch
// CSR (built once per launch)
__device__ int                 g_off[NN + 1];
__device__ int                 g_pos[NN];      // counts, then running scatter positions
__device__ int                 g_csr[EE];      // dst sorted by src

// ---------------- helpers ----------------
__device__ __forceinline__ unsigned ford(float f) {
    unsigned u = __float_as_uint(f);
    return (u >> 31) ? ~u : (u | 0x80000000u);
}
__device__ __forceinline__ float iford(unsigned u) {
    unsigned v = (u >> 31) ? (u & 0x7FFFFFFFu) : ~u;
    return __uint_as_float(v);
}

// ---------------- init: zero masks + degree counters ----------------
__global__ void k_init(  ) {
    int stride = gridDim.x * blockDim.x;
    for (int v = blockIdx.x * blockDim.x + threadIdx.x; v < NN; v += stride) {
        g_nbr[v] = 0u;
        g_known[v] = 0;
        g_pos[v] = 0;
    }
}

// ---------------- CSR build ----------------
__global__ void k_count(const int* __restrict__ src, int e) {
    int gt = blockIdx.x * blockDim.x + threadIdx.x;
    int stride = gridDim.x * blockDim.x;
    int e4 = e >> 2;
    const int4* s4 = reinterpret_cast<const int4*>(src);
    for (int i = gt; i < e4; i += stride) {
        int4 s = s4[i];
        atomicAdd(&g_pos[s.x], 1);
        atomicAdd(&g_pos[s.y], 1);
        atomicAdd(&g_pos[s.z], 1);
        atomicAdd(&g_pos[s.w], 1);
    }
    int tail = e & 3, base = e - tail;
    if (gt < tail) atomicAdd(&g_pos[src[base + gt]], 1);
}

__global__ void k_scan() {
    const int tid = threadIdx.x; // 1024 threads, one block
    const int SEG = (NN + 1023) / 1024; // 98
    int lo = tid * SEG;
    int hi = lo + SEG;
    if (lo > NN) lo = NN;
    if (hi > NN) hi = NN;
    int s = 0;
    for (int v = lo; v < hi; v++) s += g_pos[v];
    int lane = tid & 31, wid = tid >> 5;
    int x = s;
#pragma unroll
    for (int off = 1; off < 32; off <<= 1) {
        int y = __shfl_up_sync(0xffffffffu, x, off);
        if (lane >= off) x += y;
    }
    __shared__ int wsum[32];
    if (lane == 31) wsum[wid] = x;
    __syncthreads();
    if (wid == 0) {
        int w = wsum[lane];
#pragma unroll
        for (int off = 1; off < 32; off <<= 1) {
            int y = __shfl_up_sync(0xffffffffu, w, off);
            if (lane >= off) w += y;
        }
        wsum[lane] = w;
    }
    __syncthreads();
    int excl = x - s + (wid ? wsum[wid - 1] : 0);
    int run = excl;
    for (int v = lo; v < hi; v++) {
        int c = g_pos[v];
        g_off[v] = run;
        g_pos[v] = run;
        run += c;
    }
    if (tid == 1023) g_off[NN] = run;
}

__global__ void k_scatter(const int* __restrict__ src, const int* __restrict__ dst, int e) {
    int gt = blockIdx.x * blockDim.x + threadIdx.x;
    int stride = gridDim.x * blockDim.x;
    int e4 = e >> 2;
    const int4* s4 = reinterpret_cast<const int4*>(src);
    const int4* d4 = reinterpret_cast<const int4*>(dst);
    for (int i = gt; i < e4; i += stride) {
        int4 s = s4[i];
        int4 d = d4[i];
        g_csr[atomicAdd(&g_pos[s.x], 1)] = d.x;
        g_csr[atomicAdd(&g_pos[s.y], 1)] = d.y;
        g_csr[atomicAdd(&g_pos[s.z], 1)] = d.z;
        g_csr[atomicAdd(&g_pos[s.w], 1)] = d.w;
    }
    int tail = e & 3, base = e - tail;
    if (gt < tail) {
        int s = src[base + gt];
        g_csr[atomicAdd(&g_pos[s], 1)] = dst[base + gt];
    }
}

// ---------------- fused: memory step (blocks 0..CC-1) + member expansion ----------------
#define EXPB 48
__global__ void k_mem_expand(const float* __restrict__ es, const float* __restrict__ W,
                             const int* __restrict__ seeds, int t,
                             float* __restrict__ outHxes) {
    __shared__ float s_inp[KK * DD];
    __shared__ float s_q[DD];
    __shared__ float s_a[KK];
    __shared__ float s_pre[DD];
    __shared__ float s_red[4];

    const int lane = threadIdx.x & 31;

    if (blockIdx.x >= CC) {
        // ---- expand role: promote last selections to known, OR class bit into neighbors ----
        int b2 = blockIdx.x - CC;
        int per = (t == 0) ? SS : KK;
        int nm = CC * per;
        const int* list = (t == 0) ? seeds : g_last;
        int w = b2 * 4 + (threadIdx.x >> 5);
        int nwarp = EXPB * 4;
        for (int m = w; m < nm; m += nwarp) {
            int c = m / per;
            int u = list[m];
            if (lane == 0) g_known[u] = 1;
            unsigned bit = 1u << c;
            int lo = g_off[u], hi = g_off[u + 1];
            for (int j = lo + lane; j < hi; j += 32)
                atomicOr(&g_nbr[g_csr[j]], bit);
        }
        return;
    }

    // ---- memory role ----
    const int c = blockIdx.x;
    const int d = threadIdx.x; // 128 threads
    const int kk = (t == 0) ? SS : KK;
    const int* lp = (t == 0) ? (seeds + c * kk) : (g_last + c * KK);

    for (int j = 0; j < kk; j++) {
        int node = lp[j];
        s_inp[j * DD + d] = es[(size_t)node * DD + d];
    }
    float hprev = (t > 0) ? g_hx[c * DD + d] : 0.0f;
    if (t == 0) {
        float s = 0.0f;
        for (int j = 0; j < kk; j++) s += s_inp[j * DD + d];
        s_q[d] = s / (float)kk;
    } else {
        s_q[d] = hprev;
    }
    __syncthreads();

    int wid = d >> 5;
    for (int j = wid; j < kk; j += 4) {
        float p = 0.0f;
#pragma unroll
        for (int q = 0; q < 4; q++) {
            int dd = lane + 32 * q;
            p += s_inp[j * DD + dd] * s_q[dd];
        }
#pragma unroll
        for (int o = 16; o; o >>= 1) p += __shfl_xor_sync(0xffffffffu, p, o);
        if (lane == 0) s_a[j] = p / sqrtf(128.0f);
    }
    __syncthreads();
    if (d == 0) {
        float m = s_a[0];
        for (int j = 1; j < kk; j++) m = fmaxf(m, s_a[j]);
        float sum = 0.0f;
        for (int j = 0; j < kk; j++) { float e = expf(s_a[j] - m); s_a[j] = e; sum += e; }
        for (int j = 0; j < kk; j++) s_a[j] /= sum;
    }
    __syncthreads();
    float ctx = 0.0f;
    for (int j = 0; j < kk; j++) ctx += s_a[j] * s_inp[j * DD + d];
    s_pre[d] = ctx + hprev;
    __syncthreads();

    float acc = 0.0f;
    for (int i = 0; i < DD; i++) acc += s_pre[i] * W[i * DD + d];
    float h = tanhf(acc);
    g_hx[c * DD + d] = h;
    outHxes[(t * CC + c) * DD + d] = h;

    float ss = h * h;
#pragma unroll
    for (int o = 16; o; o >>= 1) ss += __shfl_xor_sync(0xffffffffu, ss, o);
    if (lane == 0) s_red[wid] = ss;
    __syncthreads();
    float ns = s_red[0] + s_red[1] + s_red[2] + s_red[3];
    g_hxn[c * DD + d] = h / (sqrtf(ns) + 1e-8f);
    if (d == 0) g_candCnt[c] = 0;
}

// ---------------- candidate compaction + cosine scoring (warp per node) ----------------
__global__ void k_compact(const float* __restrict__ es) {
    __shared__ float sh[CC * DD];
    for (int i = threadIdx.x; i < CC * DD; i += blockDim.x) sh[i] = g_hxn[i];
    __syncthreads();
    const int lane = threadIdx.x & 31;
    const int gw = (blockIdx.x * blockDim.x + threadIdx.x) >> 5;
    const int nw = (gridDim.x * blockDim.x) >> 5;
    for (int v = gw; v < NN; v += nw) {
        unsigned m = g_nbr[v];
        if (m == 0u) continue;
        if (g_known[v]) continue;
        const float4 r = reinterpret_cast<const float4*>(es)[(size_t)v * 32 + lane];
        float ss = r.x * r.x + r.y * r.y + r.z * r.z + r.w * r.w;
#pragma unroll
        for (int o = 16; o; o >>= 1) ss += __shfl_xor_sync(0xffffffffu, ss, o);
        float inv = 1.0f / (sqrtf(ss) + 1e-8f);
        while (m) {
            int c = __ffs(m) - 1;
            m &= m - 1;
            const float4 h = reinterpret_cast<const float4*>(sh + c * DD)[lane];
            float dp = r.x * h.x + r.y * h.y + r.z * h.z + r.w * h.w;
#pragma unroll
            for (int o = 16; o; o >>= 1) dp += __shfl_xor_sync(0xffffffffu, dp, o);
            if (lane == 0) {
                float score = dp * inv;
                unsigned long long key =
                    ((unsigned long long)ford(score) << 32) |
                    (unsigned long long)(0xFFFFFFFFu - (unsigned)v);
                int p = atomicAdd(&g_candCnt[c], 1);
                g_candKeys[(size_t)c * NN + p] = key;
            }
        }
    }
}

// ---------------- exact top-K per class: radix-select threshold + bitonic sort ----------------
__global__ void k_topk(float* __restrict__ outP, float* __restrict__ outE, int t) {
    const int c = blockIdx.x;
    const int tid = threadIdx.x;
    const int BD = 256;
    __shared__ unsigned int hist[4096];
    __shared__ unsigned int s_chunk[256];
    __shared__ unsigned long long sbuf[512];
    __shared__ int s_b, s_cum, s_stop, s_scnt;

    const unsigned long long* keys = g_candKeys + (size_t)c * NN;
    int cnt = g_candCnt[c];
    int r = cnt < KK ? cnt : KK;

    unsigned long long prefix = 0ULL;
    int sf = 64;
    if (cnt > 512) {
        int rr = r;
        for (int shift = 52; shift >= 4; shift -= 12) {
            for (int i = tid; i < 4096; i += BD) hist[i] = 0u;
            __syncthreads();
            for (int i = tid; i < cnt; i += BD) {
                unsigned long long key = keys[i];
                if (sf >= 64 || (key >> sf) == prefix)
                    atomicAdd(&hist[(unsigned)((key >> shift) & 0xFFFULL)], 1u);
            }
            __syncthreads();
            // parallel threshold find: suffix sums of 256 16-bucket chunks
            unsigned lsum = 0;
            int base16 = tid * 16;
#pragma unroll
            for (int j = 0; j < 16; j++) lsum += hist[base16 + j];
            s_chunk[tid] = lsum;
            __syncthreads();
            for (int off = 1; off < 256; off <<= 1) {
                unsigned add = (tid + off < 256) ? s_chunk[tid + off] : 0u;
                __syncthreads();
                s_chunk[tid] += add;
                __syncthreads();
            }
            unsigned above = (tid < 255) ? s_chunk[tid + 1] : 0u;
            if (above < (unsigned)rr && above + lsum >= (unsigned)rr) {
                unsigned cum = above;
                for (int b = base16 + 15; b >= base16; --b) {
                    unsigned h = hist[b];
                    if (cum + h >= (unsigned)rr) {
                        s_b = b;
                        s_cum = (int)cum;
                        int aboveTot = (r - rr) + (int)cum;
                        s_stop = (aboveTot + (int)h <= 256) ? 1 : 0;
                        break;
                    }
                    cum += h;
                }
            }
            __syncthreads();
            prefix = (prefix << 12) | (unsigned long long)s_b;
            rr -= s_cum;
            sf = shift;
            int stop = s_stop;
            __syncthreads();
            if (stop) break;
        }
    }
    if (tid == 0) s_scnt = 0;
    __syncthreads();
    for (int i = tid; i < cnt; i += BD) {
        unsigned long long key = keys[i];
        bool take = (sf >= 64) || ((key >> sf) >= prefix);
        if (take) {
            int p = atomicAdd(&s_scnt, 1);
            if (p < 512) sbuf[p] = key;
        }
    }
    __syncthreads();
    int sc = s_scnt < 512 ? s_scnt : 512;
    int n = (sc <= 256) ? 256 : 512;
    for (int i = tid; i < n; i += BD)
        if (i >= sc) sbuf[i] = 0ULL;
    __syncthreads();
    // bitonic sort descending, n elements (256 or 512)
    for (int kk2 = 2; kk2 <= n; kk2 <<= 1) {
        for (int j = kk2 >> 1; j > 0; j >>= 1) {
            for (int i = tid; i < n; i += BD) {
                int ixj = i ^ j;
                if (ixj > i) {
                    unsigned long long a = sbuf[i], b = sbuf[ixj];
                    bool desc = ((i & kk2) == 0);
                    if (desc ? (a < b) : (a > b)) { sbuf[i] = b; sbuf[ixj] = a; }
                }
            }
            __syncthreads();
        }
    }
    const int base = (t * CC + c) * KK;
    if (tid < KK && tid < r) {
        unsigned long long key = sbuf[tid];
        int v = (int)(0xFFFFFFFFu - (unsigned)(key & 0xFFFFFFFFull));
        outP[base + tid] = iford((unsigned)(key >> 32));
        outE[base + tid] = (float)v;
        g_last[c * KK + tid] = v;
    }
    // rare fill path: fewer than K valid candidates -> -1e9, lowest-index invalid nodes
    if (tid == 0 && r < KK) {
        int fill = r;
        for (int v = 0; v < NN && fill < KK; v++) {
            bool valid = (((g_nbr[v] >> c) & 1u) != 0u) && (g_known[v] == 0);
            if (!valid) {
                outP[base + fill] = -1e9f;
                outE[base + fill] = (float)v;
                g_last[c * KK + fill] = v;
                fill++;
            }
        }
    }
}

// ---------------- launch ----------------
extern "C" void kernel_launch(void* const* d_in, const int* in_sizes, int n_in,
                              void* d_out, int out_size) {
    const float* es    = (const float*)d_in[0];
    const int*   edges = (const int*)d_in[1];
    const int*   seeds = (const int*)d_in[2];
    const float* W     = (const float*)d_in[3];
    (void)n_in; (void)out_size;

    int e = in_sizes[1] / 2;
    const int* src = edges;
    const int* dst = edges + e;

    float* out  = (float*)d_out;
    float* outP = out;                       // [4,16,64] probs
    float* outE = out + NIT * CC * KK;       // [4,16,64] indices (as float)
    float* outH = out + 2 * NIT * CC * KK;   // [4,16,128] hx

    k_init<<<128, 256>>>();
    k_count<<<1024, 256>>>(src, e);
    k_scan<<<1, 1024>>>();
    k_scatter<<<1024, 256>>>(src, dst, e);

    for (int t = 0; t < NIT; t++) {
        k_mem_expand<<<CC + EXPB, 128>>>(es, W, seeds, t, outH);
        k_compact<<<512, 256>>>(es);
        k_topk<<<CC, 256>>>(outP, outE, t);
    }
}

// round 8
// speedup vs baseline: 1.3947x; 1.3947x over previous
#include <cuda_runtime.h>
#include <math.h>
#include <stdint.h>

#define NN 100000
#define DD 128
#define CC 16
#define SS 16
#define KK 64
#define NIT 4
#define BMW 3125          // bitmap words for 100000 bits
#define HSZ 4096          // hash slots
#define EB  184           // edge-scan blocks in fused kernel

// ---------------- persistent device state (reset every launch) ----------------
__device__ unsigned int        g_nbr[NN];      // per-node 16-bit class neighbor mask (accumulative)
__device__ unsigned char       g_known[NN];
__device__ float               g_hx[CC * DD];
__device__ float               g_hxn[CC * DD]; // normalized hx
__device__ int                 g_last[CC * KK];
__device__ int                 g_candCnt[CC];
__device__ unsigned long long  g_candKeys[(size_t)CC * NN];

// ---------------- helpers ----------------
__device__ __forceinline__ unsigned ford(float f) {
    unsigned u = __float_as_uint(f);
    return (u >> 31) ? ~u : (u | 0x80000000u);
}
__device__ __forceinline__ float iford(unsigned u) {
    unsigned v = (u >> 31) ? (u & 0x7FFFFFFFu) : ~u;
    return __uint_as_float(v);
}
__device__ __forceinline__ int hslot(unsigned v) {
    return (int)((v * 2654435761u) >> 20); // top 12 bits -> 0..4095
}

// ---------------- init ----------------
__global__ void k_init() {
    int stride = gridDim.x * blockDim.x;
    int gt = blockIdx.x * blockDim.x + threadIdx.x;
    for (int v = gt; v < NN; v += stride) {
        g_nbr[v] = 0u;
        g_known[v] = 0;
    }
    if (gt < CC) g_candCnt[gt] = 0;
}

// ---------------- fused: memory step (blocks 0..15) + edge expansion (blocks 16..) ----------
__global__ void __launch_bounds__(128) k_mem_edges(
        const float* __restrict__ es, const float* __restrict__ W,
        const int* __restrict__ seeds,
        const int* __restrict__ src, const int* __restrict__ dst, int e,
        int t, float* __restrict__ outHxes) {
    __shared__ __align__(16) unsigned char s_raw[45280];
    const int tid = threadIdx.x;
    const int lane = tid & 31;
    const int per = (t == 0) ? SS : KK;
    const int nm = CC * per;
    const int* list = (t == 0) ? seeds : g_last;

    if (blockIdx.x >= CC) {
        // ---------- edge role ----------
        unsigned* bm    = reinterpret_cast<unsigned*>(s_raw);              // 12512 B
        unsigned* hkey  = reinterpret_cast<unsigned*>(s_raw + 12512);      // 16384 B
        unsigned* hmask = reinterpret_cast<unsigned*>(s_raw + 12512 + 16384);
        const int b2 = blockIdx.x - CC;

        for (int i = tid; i < BMW; i += 128) bm[i] = 0u;
        for (int i = tid; i < HSZ; i += 128) { hkey[i] = 0u; hmask[i] = 0u; }
        __syncthreads();
        for (int m = tid; m < nm; m += 128) {
            unsigned u = (unsigned)list[m];
            unsigned bit = 1u << (m / per);
            atomicOr(&bm[u >> 5], 1u << (u & 31));
            int s = hslot(u);
            for (;;) {
                unsigned k = atomicCAS(&hkey[s], 0u, u + 1u);
                if (k == 0u || k == u + 1u) { atomicOr(&hmask[s], bit); break; }
                s = (s + 1) & (HSZ - 1);
            }
            if (b2 == 0) g_known[u] = 1; // promote to known (idempotent)
        }
        __syncthreads();

        const int e4 = e >> 2;
        const int4* s4 = reinterpret_cast<const int4*>(src);
        const int stride = EB * 128;
        int gt = b2 * 128 + tid;
        for (int i = gt; i < e4; i += stride) {
            int4 s = s4[i];
#pragma unroll
            for (int q = 0; q < 4; q++) {
                unsigned u = (unsigned)((q == 0) ? s.x : (q == 1) ? s.y : (q == 2) ? s.z : s.w);
                if ((bm[u >> 5] >> (u & 31)) & 1u) {
                    int sl = hslot(u);
                    unsigned m;
                    for (;;) {
                        unsigned k = hkey[sl];
                        if (k == u + 1u) { m = hmask[sl]; break; }
                        sl = (sl + 1) & (HSZ - 1);
                    }
                    atomicOr(&g_nbr[dst[4 * i + q]], m);
                }
            }
        }
        int tail = e & 3, tb = e - tail;
        if (b2 == 0 && tid < tail) {
            unsigned u = (unsigned)src[tb + tid];
            if ((bm[u >> 5] >> (u & 31)) & 1u) {
                int sl = hslot(u);
                unsigned m;
                for (;;) {
                    unsigned k = hkey[sl];
                    if (k == u + 1u) { m = hmask[sl]; break; }
                    sl = (sl + 1) & (HSZ - 1);
                }
                atomicOr(&g_nbr[dst[tb + tid]], m);
            }
        }
        return;
    }

    // ---------- memory role ----------
    float* s_inp = reinterpret_cast<float*>(s_raw);               // 32768 B
    float* s_q   = reinterpret_cast<float*>(s_raw + 32768);       // 512
    float* s_a   = reinterpret_cast<float*>(s_raw + 33280);       // 256
    float* s_pre = reinterpret_cast<float*>(s_raw + 33536);       // 512
    float* s_red = reinterpret_cast<float*>(s_raw + 34048);       // 16

    const int c = blockIdx.x;
    const int d = tid;
    const int kk = per;
    const int* lp = list + c * kk;

    for (int j = 0; j < kk; j++) {
        int node = lp[j];
        s_inp[j * DD + d] = es[(size_t)node * DD + d];
    }
    float hprev = (t > 0) ? g_hx[c * DD + d] : 0.0f;
    if (t == 0) {
        float s = 0.0f;
        for (int j = 0; j < kk; j++) s += s_inp[j * DD + d];
        s_q[d] = s / (float)kk;
    } else {
        s_q[d] = hprev;
    }
    __syncthreads();

    int wid = d >> 5;
    for (int j = wid; j < kk; j += 4) {
        float p = 0.0f;
#pragma unroll
        for (int q = 0; q < 4; q++) {
            int dd = lane + 32 * q;
            p += s_inp[j * DD + dd] * s_q[dd];
        }
#pragma unroll
        for (int o = 16; o; o >>= 1) p += __shfl_xor_sync(0xffffffffu, p, o);
        if (lane == 0) s_a[j] = p / sqrtf(128.0f);
    }
    __syncthreads();
    if (d == 0) {
        float m = s_a[0];
        for (int j = 1; j < kk; j++) m = fmaxf(m, s_a[j]);
        float sum = 0.0f;
        for (int j = 0; j < kk; j++) { float e2 = expf(s_a[j] - m); s_a[j] = e2; sum += e2; }
        for (int j = 0; j < kk; j++) s_a[j] /= sum;
    }
    __syncthreads();
    float ctx = 0.0f;
    for (int j = 0; j < kk; j++) ctx += s_a[j] * s_inp[j * DD + d];
    s_pre[d] = ctx + hprev;
    __syncthreads();

    float acc = 0.0f;
#pragma unroll 4
    for (int i = 0; i < DD; i++) acc += s_pre[i] * W[i * DD + d];
    float h = tanhf(acc);
    g_hx[c * DD + d] = h;
    outHxes[(t * CC + c) * DD + d] = h;

    float ss = h * h;
#pragma unroll
    for (int o = 16; o; o >>= 1) ss += __shfl_xor_sync(0xffffffffu, ss, o);
    if (lane == 0) s_red[wid] = ss;
    __syncthreads();
    float ns = s_red[0] + s_red[1] + s_red[2] + s_red[3];
    g_hxn[c * DD + d] = h / (sqrtf(ns) + 1e-8f);
}

// ---------------- candidate compaction + cosine scoring ----------------
__global__ void k_compact(const float* __restrict__ es) {
    __shared__ float sh[CC * DD];
    for (int i = threadIdx.x; i < CC * DD; i += blockDim.x) sh[i] = g_hxn[i];
    __syncthreads();
    const int lane = threadIdx.x & 31;
    const int gt = blockIdx.x * blockDim.x + threadIdx.x;
    const int stride = gridDim.x * blockDim.x;
    const int rounds = (NN + stride - 1) / stride;
    int v = gt;
    for (int rr = 0; rr < rounds; rr++, v += stride) {
        unsigned m = 0u;
        if (v < NN) {
            m = g_nbr[v];
            if (m && g_known[v]) m = 0u;
        }
        unsigned ball = __ballot_sync(0xffffffffu, m != 0u);
        while (ball) {
            int L = __ffs(ball) - 1;
            ball &= ball - 1;
            int vv = __shfl_sync(0xffffffffu, v, L);
            unsigned mm = __shfl_sync(0xffffffffu, m, L);
            const float4 r = reinterpret_cast<const float4*>(es)[(size_t)vv * 32 + lane];
            float ss = r.x * r.x + r.y * r.y + r.z * r.z + r.w * r.w;
#pragma unroll
            for (int o = 16; o; o >>= 1) ss += __shfl_xor_sync(0xffffffffu, ss, o);
            float inv = 1.0f / (sqrtf(ss) + 1e-8f);
            while (mm) {
                int c = __ffs(mm) - 1;
                mm &= mm - 1;
                const float4 h = reinterpret_cast<const float4*>(sh + c * DD)[lane];
                float dp = r.x * h.x + r.y * h.y + r.z * h.z + r.w * h.w;
#pragma unroll
                for (int o = 16; o; o >>= 1) dp += __shfl_xor_sync(0xffffffffu, dp, o);
                if (lane == 0) {
                    float score = dp * inv;
                    unsigned long long key =
                        ((unsigned long long)ford(score) << 32) |
                        (unsigned long long)(0xFFFFFFFFu - (unsigned)vv);
                    int p = atomicAdd(&g_candCnt[c], 1);
                    g_candKeys[(size_t)c * NN + p] = key;
                }
            }
        }
    }
}

// ---------------- exact top-K per class: radix-select threshold + bitonic sort ----------------
__global__ void k_topk(float* __restrict__ outP, float* __restrict__ outE, int t) {
    const int c = blockIdx.x;
    const int tid = threadIdx.x;
    const int BD = 256;
    __shared__ unsigned int hist[4096];
    __shared__ unsigned int s_chunk[256];
    __shared__ unsigned long long sbuf[512];
    __shared__ int s_b, s_cum, s_stop, s_scnt;

    const unsigned long long* keys = g_candKeys + (size_t)c * NN;
    int cnt = g_candCnt[c];
    __syncthreads();
    if (tid == 0) g_candCnt[c] = 0; // reset for next iteration's compact
    int r = cnt < KK ? cnt : KK;

    unsigned long long prefix = 0ULL;
    int sf = 64;
    if (cnt > 512) {
        int rr = r;
        for (int shift = 52; shift >= 4; shift -= 12) {
            for (int i = tid; i < 4096; i += BD) hist[i] = 0u;
            __syncthreads();
            for (int i = tid; i < cnt; i += BD) {
                unsigned long long key = keys[i];
                if (sf >= 64 || (key >> sf) == prefix)
                    atomicAdd(&hist[(unsigned)((key >> shift) & 0xFFFULL)], 1u);
            }
            __syncthreads();
            unsigned lsum = 0;
            int base16 = tid * 16;
#pragma unroll
            for (int j = 0; j < 16; j++) lsum += hist[base16 + j];
            s_chunk[tid] = lsum;
            __syncthreads();
            for (int off = 1; off < 256; off <<= 1) {
                unsigned add = (tid + off < 256) ? s_chunk[tid + off] : 0u;
                __syncthreads();
                s_chunk[tid] += add;
                __syncthreads();
            }
            unsigned above = (tid < 255) ? s_chunk[tid + 1] : 0u;
            if (above < (unsigned)rr && above + lsum >= (unsigned)rr) {
                unsigned cum = above;
                for (int b = base16 + 15; b >= base16; --b) {
                    unsigned h = hist[b];
                    if (cum + h >= (unsigned)rr) {
                        s_b = b;
                        s_cum = (int)cum;
                        int aboveTot = (r - rr) + (int)cum;
                        s_stop = (aboveTot + (int)h <= 256) ? 1 : 0;
                        break;
                    }
                    cum += h;
                }
            }
            __syncthreads();
            prefix = (prefix << 12) | (unsigned long long)s_b;
            rr -= s_cum;
            sf = shift;
            int stop = s_stop;
            __syncthreads();
            if (stop) break;
        }
    }
    if (tid == 0) s_scnt = 0;
    __syncthreads();
    for (int i = tid; i < cnt; i += BD) {
        unsigned long long key = keys[i];
        bool take = (sf >= 64) || ((key >> sf) >= prefix);
        if (take) {
            int p = atomicAdd(&s_scnt, 1);
            if (p < 512) sbuf[p] = key;
        }
    }
    __syncthreads();
    int sc = s_scnt < 512 ? s_scnt : 512;
    int n = (sc <= 256) ? 256 : 512;
    for (int i = tid; i < n; i += BD)
        if (i >= sc) sbuf[i] = 0ULL;
    __syncthreads();
    for (int kk2 = 2; kk2 <= n; kk2 <<= 1) {
        for (int j = kk2 >> 1; j > 0; j >>= 1) {
            for (int i = tid; i < n; i += BD) {
                int ixj = i ^ j;
                if (ixj > i) {
                    unsigned long long a = sbuf[i], b = sbuf[ixj];
                    bool desc = ((i & kk2) == 0);
                    if (desc ? (a < b) : (a > b)) { sbuf[i] = b; sbuf[ixj] = a; }
                }
            }
            __syncthreads();
        }
    }
    const int base = (t * CC + c) * KK;
    if (tid < KK && tid < r) {
        unsigned long long key = sbuf[tid];
        int v = (int)(0xFFFFFFFFu - (unsigned)(key & 0xFFFFFFFFull));
        outP[base + tid] = iford((unsigned)(key >> 32));
        outE[base + tid] = (float)v;
        g_last[c * KK + tid] = v;
    }
    if (tid == 0 && r < KK) {
        int fill = r;
        for (int v = 0; v < NN && fill < KK; v++) {
            bool valid = (((g_nbr[v] >> c) & 1u) != 0u) && (g_known[v] == 0);
            if (!valid) {
                outP[base + fill] = -1e9f;
                outE[base + fill] = (float)v;
                g_last[c * KK + fill] = v;
                fill++;
            }
        }
    }
}

// ---------------- launch ----------------
extern "C" void kernel_launch(void* const* d_in, const int* in_sizes, int n_in,
                              void* d_out, int out_size) {
    const float* es    = (const float*)d_in[0];
    const int*   edges = (const int*)d_in[1];
    const int*   seeds = (const int*)d_in[2];
    const float* W     = (const float*)d_in[3];
    (void)n_in; (void)out_size;

    int e = in_sizes[1] / 2;
    const int* src = edges;
    const int* dst = edges + e;

    float* out  = (float*)d_out;
    float* outP = out;
    float* outE = out + NIT * CC * KK;
    float* outH = out + 2 * NIT * CC * KK;

    k_init<<<128, 256>>>();
    for (int t = 0; t < NIT; t++) {
        k_mem_edges<<<CC + EB, 128>>>(es, W, seeds, src, dst, e, t, outH);
        k_compact<<<256, 256>>>(es);
        k_topk<<<CC, 256>>>(outP, outE, t);
    }
}

// round 9
// speedup vs baseline: 1.6722x; 1.1989x over previous
#include <cuda_runtime.h>
#include <math.h>
#include <stdint.h>

#define NN 100000
#define DD 128
#define CC 16
#define SS 16
#define KK 64
#define NIT 4
#define BMW 3125          // bitmap words for 100000 bits
#define HSZ 4096          // hash slots
#define EB  368           // edge-scan blocks in fused kernel
#define KNOWN 0x80000000u

// ---------------- persistent device state (reset every launch) ----------------
__device__ unsigned int        g_nbr[NN];      // bits 0..15 class neighbor mask, bit31 = known
__device__ float               g_hx[CC * DD];
__device__ float               g_hxn[CC * DD];
__device__ int                 g_last[CC * KK];
__device__ int                 g_candCnt[CC];
__device__ unsigned long long  g_candKeys[(size_t)CC * NN];

// ---------------- helpers ----------------
__device__ __forceinline__ unsigned ford(float f) {
    unsigned u = __float_as_uint(f);
    return (u >> 31) ? ~u : (u | 0x80000000u);
}
__device__ __forceinline__ float iford(unsigned u) {
    unsigned v = (u >> 31) ? (u & 0x7FFFFFFFu) : ~u;
    return __uint_as_float(v);
}
__device__ __forceinline__ int hslot(unsigned v) {
    return (int)((v * 2654435761u) >> 20);
}

// ---------------- init ----------------
__global__ void k_init() {
    int stride = gridDim.x * blockDim.x;
    int gt = blockIdx.x * blockDim.x + threadIdx.x;
    for (int v = gt; v < NN; v += stride) g_nbr[v] = 0u;
    if (gt < CC) g_candCnt[gt] = 0;
}

// ---------------- fused: memory step (blocks 0..15) + edge expansion ----------
__global__ void __launch_bounds__(128) k_mem_edges(
        const float* __restrict__ es, const float* __restrict__ W,
        const int* __restrict__ seeds,
        const int* __restrict__ src, const int* __restrict__ dst, int e,
        int t, float* __restrict__ outHxes) {
    __shared__ __align__(16) unsigned char s_raw[45280];
    const int tid = threadIdx.x;
    const int lane = tid & 31;
    const int per = (t == 0) ? SS : KK;
    const int nm = CC * per;
    const int* list = (t == 0) ? seeds : g_last;

    if (blockIdx.x >= CC) {
        // ---------- edge role ----------
        unsigned* bm    = reinterpret_cast<unsigned*>(s_raw);              // 12512 B
        unsigned* hkey  = reinterpret_cast<unsigned*>(s_raw + 12512);      // 16384 B
        unsigned* hmask = reinterpret_cast<unsigned*>(s_raw + 12512 + 16384);
        const int b2 = blockIdx.x - CC;

        for (int i = tid; i < BMW; i += 128) bm[i] = 0u;
        for (int i = tid; i < HSZ; i += 128) { hkey[i] = 0u; hmask[i] = 0u; }
        __syncthreads();
        for (int m = tid; m < nm; m += 128) {
            unsigned u = (unsigned)list[m];
            unsigned bit = 1u << (m / per);
            atomicOr(&bm[u >> 5], 1u << (u & 31));
            int s = hslot(u);
            for (;;) {
                unsigned k = atomicCAS(&hkey[s], 0u, u + 1u);
                if (k == 0u || k == u + 1u) { atomicOr(&hmask[s], bit); break; }
                s = (s + 1) & (HSZ - 1);
            }
            if (b2 == 0) atomicOr(&g_nbr[u], KNOWN); // promote to known
        }
        __syncthreads();

        const int e4 = e >> 2;
        const int4* s4 = reinterpret_cast<const int4*>(src);
        const int stride = EB * 128;
        int gt = b2 * 128 + tid;
#pragma unroll 4
        for (int i = gt; i < e4; i += stride) {
            int4 s = s4[i];
#pragma unroll
            for (int q = 0; q < 4; q++) {
                unsigned u = (unsigned)((q == 0) ? s.x : (q == 1) ? s.y : (q == 2) ? s.z : s.w);
                if ((bm[u >> 5] >> (u & 31)) & 1u) {
                    int sl = hslot(u);
                    unsigned m;
                    for (;;) {
                        unsigned k = hkey[sl];
                        if (k == u + 1u) { m = hmask[sl]; break; }
                        sl = (sl + 1) & (HSZ - 1);
                    }
                    atomicOr(&g_nbr[dst[4 * i + q]], m);
                }
            }
        }
        int tail = e & 3, tb = e - tail;
        if (b2 == 0 && tid < tail) {
            unsigned u = (unsigned)src[tb + tid];
            if ((bm[u >> 5] >> (u & 31)) & 1u) {
                int sl = hslot(u);
                unsigned m;
                for (;;) {
                    unsigned k = hkey[sl];
                    if (k == u + 1u) { m = hmask[sl]; break; }
                    sl = (sl + 1) & (HSZ - 1);
                }
                atomicOr(&g_nbr[dst[tb + tid]], m);
            }
        }
        return;
    }

    // ---------- memory role ----------
    float* s_inp = reinterpret_cast<float*>(s_raw);
    float* s_q   = reinterpret_cast<float*>(s_raw + 32768);
    float* s_a   = reinterpret_cast<float*>(s_raw + 33280);
    float* s_pre = reinterpret_cast<float*>(s_raw + 33536);
    float* s_red = reinterpret_cast<float*>(s_raw + 34048);

    const int c = blockIdx.x;
    const int d = tid;
    const int kk = per;
    const int* lp = list + c * kk;

    for (int j = 0; j < kk; j++) {
        int node = lp[j];
        s_inp[j * DD + d] = es[(size_t)node * DD + d];
    }
    float hprev = (t > 0) ? g_hx[c * DD + d] : 0.0f;
    if (t == 0) {
        float s = 0.0f;
        for (int j = 0; j < kk; j++) s += s_inp[j * DD + d];
        s_q[d] = s / (float)kk;
    } else {
        s_q[d] = hprev;
    }
    __syncthreads();

    int wid = d >> 5;
    for (int j = wid; j < kk; j += 4) {
        float p = 0.0f;
#pragma unroll
        for (int q = 0; q < 4; q++) {
            int dd = lane + 32 * q;
            p += s_inp[j * DD + dd] * s_q[dd];
        }
#pragma unroll
        for (int o = 16; o; o >>= 1) p += __shfl_xor_sync(0xffffffffu, p, o);
        if (lane == 0) s_a[j] = p / sqrtf(128.0f);
    }
    __syncthreads();
    if (d == 0) {
        float m = s_a[0];
        for (int j = 1; j < kk; j++) m = fmaxf(m, s_a[j]);
        float sum = 0.0f;
        for (int j = 0; j < kk; j++) { float e2 = expf(s_a[j] - m); s_a[j] = e2; sum += e2; }
        for (int j = 0; j < kk; j++) s_a[j] /= sum;
    }
    __syncthreads();
    float ctx = 0.0f;
    for (int j = 0; j < kk; j++) ctx += s_a[j] * s_inp[j * DD + d];
    s_pre[d] = ctx + hprev;
    __syncthreads();

    float acc = 0.0f;
#pragma unroll 4
    for (int i = 0; i < DD; i++) acc += s_pre[i] * W[i * DD + d];
    float h = tanhf(acc);
    g_hx[c * DD + d] = h;
    outHxes[(t * CC + c) * DD + d] = h;

    float ss = h * h;
#pragma unroll
    for (int o = 16; o; o >>= 1) ss += __shfl_xor_sync(0xffffffffu, ss, o);
    if (lane == 0) s_red[wid] = ss;
    __syncthreads();
    float ns = s_red[0] + s_red[1] + s_red[2] + s_red[3];
    g_hxn[c * DD + d] = h / (sqrtf(ns) + 1e-8f);
}

// ---------------- candidate compaction + cosine scoring ----------------
__global__ void k_compact(const float* __restrict__ es) {
    __shared__ float sh[CC * DD];
    for (int i = threadIdx.x; i < CC * DD; i += blockDim.x) sh[i] = g_hxn[i];
    __syncthreads();
    const int lane = threadIdx.x & 31;
    const int gt = blockIdx.x * blockDim.x + threadIdx.x;
    const int stride = gridDim.x * blockDim.x;
    const int rounds = (NN + stride - 1) / stride;
    int v = gt;
    for (int rr = 0; rr < rounds; rr++, v += stride) {
        unsigned m = 0u;
        if (v < NN) {
            m = g_nbr[v];
            if (m & KNOWN) m = 0u;
            else m &= 0xFFFFu;
        }
        unsigned ball = __ballot_sync(0xffffffffu, m != 0u);
        while (ball) {
            int L = __ffs(ball) - 1;
            ball &= ball - 1;
            int vv = __shfl_sync(0xffffffffu, v, L);
            unsigned mm = __shfl_sync(0xffffffffu, m, L);
            const float4 r = reinterpret_cast<const float4*>(es)[(size_t)vv * 32 + lane];
            float ss = r.x * r.x + r.y * r.y + r.z * r.z + r.w * r.w;
#pragma unroll
            for (int o = 16; o; o >>= 1) ss += __shfl_xor_sync(0xffffffffu, ss, o);
            float inv = 1.0f / (sqrtf(ss) + 1e-8f);
            while (mm) {
                int c = __ffs(mm) - 1;
                mm &= mm - 1;
                const float4 h = reinterpret_cast<const float4*>(sh + c * DD)[lane];
                float dp = r.x * h.x + r.y * h.y + r.z * h.z + r.w * h.w;
#pragma unroll
                for (int o = 16; o; o >>= 1) dp += __shfl_xor_sync(0xffffffffu, dp, o);
                if (lane == 0) {
                    float score = dp * inv;
                    unsigned long long key =
                        ((unsigned long long)ford(score) << 32) |
                        (unsigned long long)(0xFFFFFFFFu - (unsigned)vv);
                    int p = atomicAdd(&g_candCnt[c], 1);
                    g_candKeys[(size_t)c * NN + p] = key;
                }
            }
        }
    }
}

// ---------------- exact top-K per class (1024 threads, low-barrier) ----------------
__global__ void __launch_bounds__(1024) k_topk(float* __restrict__ outP,
                                               float* __restrict__ outE, int t) {
    const int c = blockIdx.x;
    const int tid = threadIdx.x;
    const int lane = tid & 31;
    const int wid = tid >> 5;
    __shared__ unsigned int hist[4096];
    __shared__ unsigned int s_wsum[32];
    __shared__ unsigned long long sbuf[512];
    __shared__ int s_b, s_cum, s_stop, s_scnt;

    const unsigned long long* keys = g_candKeys + (size_t)c * NN;
    int cnt = g_candCnt[c];
    __syncthreads();
    if (tid == 0) g_candCnt[c] = 0; // reset for next iteration's compact
    int r = cnt < KK ? cnt : KK;

    unsigned long long prefix = 0ULL;
    int sf = 64;
    if (cnt > 512) {
        int rr = r;
        for (int shift = 52; shift >= 4; shift -= 12) {
            for (int j = tid; j < 4096; j += 1024) hist[j] = 0u;
            __syncthreads();
            for (int i = tid; i < cnt; i += 1024) {
                unsigned long long key = keys[i];
                if (sf >= 64 || (key >> sf) == prefix)
                    atomicAdd(&hist[(unsigned)((key >> shift) & 0xFFFULL)], 1u);
            }
            __syncthreads();
            // local sum of this thread's 4 buckets
            int b4 = tid * 4;
            unsigned lsum = hist[b4] + hist[b4 + 1] + hist[b4 + 2] + hist[b4 + 3];
            // warp inclusive suffix scan
            unsigned x = lsum;
#pragma unroll
            for (int off = 1; off < 32; off <<= 1) {
                unsigned y = __shfl_down_sync(0xffffffffu, x, off);
                if (lane + off < 32) x += y;
            }
            if (lane == 0) s_wsum[wid] = x;
            __syncthreads();
            if (wid == 0) {
                unsigned w = s_wsum[lane];
                unsigned own = w;
#pragma unroll
                for (int off = 1; off < 32; off <<= 1) {
                    unsigned y = __shfl_down_sync(0xffffffffu, w, off);
                    if (lane + off < 32) w += y;
                }
                s_wsum[lane] = w - own; // exclusive: sum of warps > lane
            }
            __syncthreads();
            unsigned incl = x + s_wsum[wid];  // sum over threads >= tid
            unsigned above = incl - lsum;     // sum over threads > tid
            if (above < (unsigned)rr && incl >= (unsigned)rr) {
                unsigned cum = above;
                for (int b = b4 + 3; b >= b4; --b) {
                    unsigned h = hist[b];
                    if (cum + h >= (unsigned)rr) {
                        s_b = b;
                        s_cum = (int)cum;
                        int aboveTot = (r - rr) + (int)cum;
                        s_stop = (aboveTot + (int)h <= 256) ? 1 : 0;
                        break;
                    }
                    cum += h;
                }
            }
            __syncthreads();
            prefix = (prefix << 12) | (unsigned long long)s_b;
            rr -= s_cum;
            sf = shift;
            int stop = s_stop;
            __syncthreads();
            if (stop) break;
        }
    }
    if (tid == 0) s_scnt = 0;
    __syncthreads();
    for (int i = tid; i < cnt; i += 1024) {
        unsigned long long key = keys[i];
        bool take = (sf >= 64) || ((key >> sf) >= prefix);
        if (take) {
            int p = atomicAdd(&s_scnt, 1);
            if (p < 512) sbuf[p] = key;
        }
    }
    __syncthreads();
    int sc = s_scnt < 512 ? s_scnt : 512;
    int n = (sc <= 256) ? 256 : 512;
    if (tid < n && tid >= sc) sbuf[tid] = 0ULL;
    __syncthreads();
    for (int kk2 = 2; kk2 <= n; kk2 <<= 1) {
        for (int j = kk2 >> 1; j > 0; j >>= 1) {
            if (tid < n) {
                int ixj = tid ^ j;
                if (ixj > tid) {
                    unsigned long long a = sbuf[tid], b = sbuf[ixj];
                    bool desc = ((tid & kk2) == 0);
                    if (desc ? (a < b) : (a > b)) { sbuf[tid] = b; sbuf[ixj] = a; }
                }
            }
            __syncthreads();
        }
    }
    const int base = (t * CC + c) * KK;
    if (tid < KK && tid < r) {
        unsigned long long key = sbuf[tid];
        int v = (int)(0xFFFFFFFFu - (unsigned)(key & 0xFFFFFFFFull));
        outP[base + tid] = iford((unsigned)(key >> 32));
        outE[base + tid] = (float)v;
        g_last[c * KK + tid] = v;
    }
    if (tid == 0 && r < KK) {
        int fill = r;
        for (int v = 0; v < NN && fill < KK; v++) {
            unsigned m = g_nbr[v];
            bool valid = (((m >> c) & 1u) != 0u) && !(m & KNOWN);
            if (!valid) {
                outP[base + fill] = -1e9f;
                outE[base + fill] = (float)v;
                g_last[c * KK + fill] = v;
                fill++;
            }
        }
    }
}

// ---------------- launch ----------------
extern "C" void kernel_launch(void* const* d_in, const int* in_sizes, int n_in,
                              void* d_out, int out_size) {
    const float* es    = (const float*)d_in[0];
    const int*   edges = (const int*)d_in[1];
    const int*   seeds = (const int*)d_in[2];
    const float* W     = (const float*)d_in[3];
    (void)n_in; (void)out_size;

    int e = in_sizes[1] / 2;
    const int* src = edges;
    const int* dst = edges + e;

    float* out  = (float*)d_out;
    float* outP = out;
    float* outE = out + NIT * CC * KK;
    float* outH = out + 2 * NIT * CC * KK;

    k_init<<<128, 256>>>();
    for (int t = 0; t < NIT; t++) {
        k_mem_edges<<<CC + EB, 128>>>(es, W, seeds, src, dst, e, t, outH);
        k_compact<<<256, 256>>>(es);
        k_topk<<<CC, 1024>>>(outP, outE, t);
    }
}